// round 16
// baseline (speedup 1.0000x reference)
#include <cuda_runtime.h>
#include <cuda_bf16.h>

#define Bb 8
#define Nn 128
#define Gg 100
#define Tt 24
#define ITERS 40
#define LRc 2e-4f
#define TWO_RHO 20.0f
#define VOLLc 1000.0f
#define VOSPc 50.0f

#define THR  256
#define NWRP 8
#define SPW  8               // scenarios per warp (8*8 = 64 per block)
#define NSC  64              // scenarios per block

#define TG   (Tt*Gg)         // 2400
#define BTG  (Bb*TG)         // 19200
#define BN   (Bb*Nn)         // 1024
#define BT   (Bb*Tt)         // 192
#define GRID (BT*2)          // 384 blocks, 2 siblings per (b,t)
#define BPB  48              // blocks per batch

// dynamic smem layout (in floats)
#define U7_OFF  12800        // after 6400 float2 (dup,ddn interleaved)
#define U8_OFF  (U7_OFF + NWRP*104)
#define DYN_FLOATS (U8_OFF + NWRP*104)   // 14464 floats = 57856 B

// ---------------- device state (cross-block only) ----------------
__device__ float d_Pbuf[2][BTG];
__device__ float d_Rup[BTG], d_Rdn[BTG];       // written last iter only
__device__ float d_QmaxP[2][BT], d_QminP[2][BT];
__device__ float d_QnP[2][BT*Nn];              // parity buffers
__device__ float d_U7P[BT*2*Gg], d_U8P[BT*2*Gg];

// ---------------- barriers (launch-safe gen/count) ----------------
__device__ unsigned g_cntB[Bb*32];
__device__ volatile unsigned g_genB[Bb*32];
__device__ unsigned g_cntP[BT*8];
__device__ volatile unsigned g_genP[BT*8];

__device__ __forceinline__ void batch_barrier(int b) {
    __syncthreads();
    if (threadIdx.x == 0) {
        int idx = b << 5;
        __threadfence();
        unsigned gen = g_genB[idx];
        if (atomicAdd(&g_cntB[idx], 1u) == (unsigned)(BPB - 1)) {
            g_cntB[idx] = 0;
            __threadfence();
            g_genB[idx] = gen + 1u;
        } else {
            while (g_genB[idx] == gen) __nanosleep(16);
        }
        __threadfence();
    }
    __syncthreads();
}

__device__ __forceinline__ void pair_barrier(int bt) {
    __syncthreads();
    if (threadIdx.x == 0) {
        int idx = bt << 3;
        __threadfence();
        unsigned gen = g_genP[idx];
        if (atomicAdd(&g_cntP[idx], 1u) == 1u) {
            g_cntP[idx] = 0;
            __threadfence();
            g_genP[idx] = gen + 1u;
        } else {
            while (g_genP[idx] == gen) __nanosleep(16);
        }
        __threadfence();
    }
    __syncthreads();
}

__device__ __forceinline__ float wsum(float v) {
    #pragma unroll
    for (int o = 16; o; o >>= 1) v += __shfl_down_sync(0xffffffffu, v, o);
    return v;
}
__device__ __forceinline__ void wsum2x(float& a, float& b) {
    #pragma unroll
    for (int o = 16; o; o >>= 1) {
        a += __shfl_xor_sync(0xffffffffu, a, o);
        b += __shfl_xor_sync(0xffffffffu, b, o);
    }
}
__device__ __forceinline__ void wsum2d(float& a, float& b) {
    #pragma unroll
    for (int o = 16; o; o >>= 1) {
        a += __shfl_down_sync(0xffffffffu, a, o);
        b += __shfl_down_sync(0xffffffffu, b, o);
    }
}

// ---------------- the whole solver, one launch ----------------
__global__ __launch_bounds__(THR, 3) void solver(
    const float* __restrict__ fc,   const float* __restrict__ omega,
    const float* __restrict__ omn,  const float* __restrict__ omx,
    const float* __restrict__ eps_, const float* __restrict__ pmin_,
    const float* __restrict__ pmax_,const float* __restrict__ bG,
    const float* __restrict__ cG,   float* __restrict__ out)
{
    extern __shared__ float dyn[];
    float2* duo = (float2*)dyn;          // [64][100] (dup, ddn)
    float* u7st = dyn + U7_OFF;          // [8][104]
    float* u8st = dyn + U8_OFF;          // [8][104]

    int blk = blockIdx.x, tid = threadIdx.x;
    int w = tid >> 5, l = tid & 31;
    int nc = blk & 1;
    int bt = blk >> 1;
    int t = bt % Tt, b = bt / Tt;
    int n0 = nc * NSC;

    __shared__ float shLS[NSC], shSP[NSC], shOM[NSC], shWQ[NSC];
    __shared__ float sRu[Gg], sRd[Gg];
    __shared__ float sdux[Gg], sddx[Gg], sdui[Gg], sddi[Gg];
    __shared__ float sred[32];
    __shared__ float shQm[Tt], shQi[Tt];
    __shared__ float sQn2[128];
    __shared__ float shc[8];
    __shared__ float shGamma, sLSx, sSPx, sLSi, sSPi;
    __shared__ float sFC, sOMN, sOMX, sEPS;

    // per-thread constants
    float bgv[4];
    #pragma unroll
    for (int j = 0; j < 4; ++j) {
        int g = l + 32*j;
        bgv[j] = (g < Gg) ? bG[g] : 0.f;
    }
    float bgs = 0.f, pmnv = 0.f, pmxv = 0.f;
    if (tid < Gg) { bgs = bG[tid]; pmnv = pmin_[tid]; pmxv = pmax_[tid]; }

    // ---- init ----
    for (int i = tid; i < NSC*Gg; i += THR) duo[i] = make_float2(0.f, 0.f);
    float dmx = 0.f, dmn = 0.f;
    if (tid < Nn) {
        #pragma unroll 4
        for (int tt = 0; tt < Tt; ++tt) {
            float om = omega[(b*Nn + tid)*Tt + tt];
            dmx += omx[b*Tt + tt] - om;
            dmn += om - omn[b*Tt + tt];
        }
    }
    if (tid < NSC) {
        shLS[tid] = 0.f; shSP[tid] = 0.f;
        shOM[tid] = omega[(b*Nn + n0 + tid)*Tt + t];
    }
    if (tid < Gg) {
        sRu[tid] = 0.f; sRd[tid] = 0.f;
        sdux[tid] = 0.f; sddx[tid] = 0.f; sdui[tid] = 0.f; sddi[tid] = 0.f;
    }
    if (tid == 0) {
        shGamma = 0.f; sLSx = 0.f; sSPx = 0.f; sLSi = 0.f; sSPi = 0.f;
        sFC = fc[bt]; sOMN = omn[bt]; sOMX = omx[bt]; sEPS = eps_[b];
    }
    __syncthreads();

    for (int it = 0; it < ITERS; ++it) {
        int pr = it & 1, pw = pr ^ 1;

        // ============ prologue: phi weights + gamma ============
        float gamma_old = shGamma;
        float qpart = 0.f;
        if (it > 0) {
            if (tid < Tt) shQm[tid] = __ldcg(&d_QmaxP[pr][b*Tt + tid]);
            else if (tid >= 32 && tid < 32 + Tt) shQi[tid-32] = __ldcg(&d_QminP[pr][b*Tt + tid - 32]);
            // Qn split in two 12-term halves across all 256 threads
            int n = tid & 127, h = tid >> 7;
            int t0 = h * 12;
            #pragma unroll 12
            for (int k = 0; k < 12; ++k)
                qpart += __ldcg(&d_QnP[pr][(b*Tt + t0 + k)*Nn + n]);
            if (h) sQn2[n] = qpart;
        }
        __syncthreads();

        float wa = 0.f, wb = 0.f;
        if (tid < Nn) {
            float wq;
            if (it == 0) { wq = 0.5f; wa = 0.25f; wb = 0.25f; }
            else {
                float Qmax = 0.f, Qmin = 0.f;
                #pragma unroll 8
                for (int tt = 0; tt < Tt; ++tt) { Qmax += shQm[tt]; Qmin += shQi[tt]; }
                float Qn = qpart + sQn2[tid];
                float Ap = Qmax - gamma_old * dmx;
                float Bp = Qmin - gamma_old * dmn;
                float M  = fmaxf(Ap, Bp);
                wq = (Qn > M) ? 1.f : ((Qn == M) ? 0.5f : 0.f);
                float aw = (Ap > Bp) ? 1.f : ((Ap == Bp) ? 0.5f : 0.f);
                float bw = (Bp > Ap) ? 1.f : ((Ap == Bp) ? 0.5f : 0.f);
                float wm = 1.f - wq;
                wa = wm * aw; wb = wm * bw;
            }
            if (tid >= n0 && tid < n0 + NSC)
                shWQ[tid - n0] = wq * (1.f / (float)Nn);
        }
        if (w < 4) {
            float v0 = wsum(wa), v1 = wsum(wb), v2 = wsum(wa * dmx), v3 = wsum(wb * dmn);
            if (l == 0) { sred[w] = v0; sred[4+w] = v1; sred[8+w] = v2; sred[12+w] = v3; }
        }
        __syncthreads();
        if (tid == 0) {
            float A = sred[0]+sred[1]+sred[2]+sred[3];
            float B = sred[4]+sred[5]+sred[6]+sred[7];
            float C = sred[8]+sred[9]+sred[10]+sred[11];
            float D = sred[12]+sred[13]+sred[14]+sred[15];
            float inv = 1.f / (float)Nn;
            shc[3] = A*inv; shc[4] = B*inv;
            shGamma = fmaxf(gamma_old - LRc * (sEPS - C*inv - D*inv), 0.f);
        }
        __syncthreads();

        // ============ big phase: warp w -> local scenarios w*8..w*8+7 ======
        float Ruv[4], Rdv[4];
        #pragma unroll
        for (int j = 0; j < 4; ++j) {
            int g = l + 32*j;
            Ruv[j] = (g < Gg) ? sRu[g] : 0.f;
            Rdv[j] = (g < Gg) ? sRd[g] : 0.f;
        }
        float u7a[4] = {0,0,0,0}, u8a[4] = {0,0,0,0};
        #pragma unroll
        for (int sp = 0; sp < SPW/2; ++sp) {
            int si0 = w*SPW + 2*sp, si1 = si0 + 1;
            int r0 = si0*Gg, r1 = si1*Gg;
            float du0[4], dd0[4], du1[4], dd1[4];
            #pragma unroll
            for (int j = 0; j < 4; ++j) {
                int g = l + 32*j;
                if (g < Gg) {
                    float2 v0 = duo[r0 + g]; du0[j] = v0.x; dd0[j] = v0.y;
                    float2 v1 = duo[r1 + g]; du1[j] = v1.x; dd1[j] = v1.y;
                } else { du0[j]=dd0[j]=du1[j]=dd1[j]=0.f; }
            }
            float r20 = (du0[0]-dd0[0]) + (du0[1]-dd0[1]) + (du0[2]-dd0[2]) + (du0[3]-dd0[3]);
            float r21 = (du1[0]-dd1[0]) + (du1[1]-dd1[1]) + (du1[2]-dd1[2]) + (du1[3]-dd1[3]);
            wsum2x(r20, r21);
            r20 += shLS[si0] - shSP[si0] - shOM[si0];
            r21 += shLS[si1] - shSP[si1] - shOM[si1];
            float wq0 = shWQ[si0], wq1 = shWQ[si1];
            float q0 = 0.f, q1 = 0.f;
            #pragma unroll
            for (int j = 0; j < 4; ++j) {
                int g = l + 32*j;
                if (g < Gg) {
                    float rtu = 2.0f * bgv[j], rtd = 0.5f * bgv[j];
                    float rl7 = fmaxf(du0[j] - Ruv[j], 0.f);
                    float rl8 = fmaxf(dd0[j] - Rdv[j], 0.f);
                    u7a[j] += rl7; u8a[j] += rl8;
                    float ndu = fmaxf(du0[j] - LRc * (wq0*rtu + TWO_RHO * (r20 + rl7)), 0.f);
                    float ndd = fmaxf(dd0[j] - LRc * (wq0*rtd + TWO_RHO * (rl8 - r20)), 0.f);
                    duo[r0 + g] = make_float2(ndu, ndd);
                    q0 += rtu*ndu + rtd*ndd;
                    rl7 = fmaxf(du1[j] - Ruv[j], 0.f);
                    rl8 = fmaxf(dd1[j] - Rdv[j], 0.f);
                    u7a[j] += rl7; u8a[j] += rl8;
                    ndu = fmaxf(du1[j] - LRc * (wq1*rtu + TWO_RHO * (r21 + rl7)), 0.f);
                    ndd = fmaxf(dd1[j] - LRc * (wq1*rtd + TWO_RHO * (rl8 - r21)), 0.f);
                    duo[r1 + g] = make_float2(ndu, ndd);
                    q1 += rtu*ndu + rtd*ndd;
                }
            }
            float qls0 = 0.f, qls1 = 0.f;
            if (l == 0) {
                float lsn = fmaxf(shLS[si0] - LRc * (wq0*VOLLc + TWO_RHO*r20), 0.f);
                float spn = fmaxf(shSP[si0] - LRc * (wq0*VOSPc - TWO_RHO*r20), 0.f);
                shLS[si0] = lsn; shSP[si0] = spn;
                qls0 = VOLLc*lsn + VOSPc*spn;
                lsn = fmaxf(shLS[si1] - LRc * (wq1*VOLLc + TWO_RHO*r21), 0.f);
                spn = fmaxf(shSP[si1] - LRc * (wq1*VOSPc - TWO_RHO*r21), 0.f);
                shLS[si1] = lsn; shSP[si1] = spn;
                qls1 = VOLLc*lsn + VOSPc*spn;
            }
            wsum2d(q0, q1);
            if (l == 0) {
                __stcg(&d_QnP[pw][bt*Nn + n0 + si0], q0 + qls0);
                __stcg(&d_QnP[pw][bt*Nn + n0 + si1], q1 + qls1);
            }
        }
        // stage per-warp U7/U8; publish sibling partial for the partner
        #pragma unroll
        for (int j = 0; j < 4; ++j) {
            int g = l + 32*j;
            if (g < Gg) { u7st[w*104 + g] = u7a[j]; u8st[w*104 + g] = u8a[j]; }
        }
        __syncthreads();
        if (tid < 200) {
            int g = (tid < 100) ? tid : tid - 100;
            float* src = (tid < 100) ? u7st : u8st;
            float s = 0.f;
            #pragma unroll
            for (int ww = 0; ww < NWRP; ++ww) s += src[ww*104 + g];
            if (tid < 100) __stcg(&d_U7P[(bt*2 + nc)*Gg + g], s);
            else           __stcg(&d_U8P[(bt*2 + nc)*Gg + g], s);
        }

        pair_barrier(bt);     // sibling U7/U8 partials visible

        // ============ small phase (duplicated in both siblings) ============
        {
            int g = tid;
            bool act = (g < Gg);
            int idx = bt*Gg + g;
            float P=0,Pm=0,Pp=0,Rux=0,Rdx=0,dux=0,ddx=0,dui=0,ddi=0,U7=0,U8=0;
            if (act) {
                if (it == 0) { float pv = 0.5f*(pmnv + pmxv); P = pv; Pm = pv; Pp = pv; }
                else {
                    P = __ldcg(&d_Pbuf[pr][idx]);
                    if (t > 0)      Pm = __ldcg(&d_Pbuf[pr][idx - Gg]);
                    if (t < Tt - 1) Pp = __ldcg(&d_Pbuf[pr][idx + Gg]);
                }
                Rux = sRu[g]; Rdx = sRd[g];
                dux = sdux[g]; ddx = sddx[g]; dui = sdui[g]; ddi = sddi[g];
                float own7 = 0.f, own8 = 0.f;
                #pragma unroll
                for (int ww = 0; ww < NWRP; ++ww) {
                    own7 += u7st[ww*104 + g];
                    own8 += u8st[ww*104 + g];
                }
                U7 = own7 + __ldcg(&d_U7P[(bt*2 + (1 - nc))*Gg + g]);
                U8 = own8 + __ldcg(&d_U8P[(bt*2 + (1 - nc))*Gg + g]);
            }
            float s1 = 0.f, s3 = 0.f, s4 = 0.f;
            if (act) { s1 = P; s3 = dux - ddx; s4 = dui - ddi; }
            if (w < 4) {
                s1 = wsum(s1); s3 = wsum(s3); s4 = wsum(s4);
                if (l == 0) { sred[16+w] = s1; sred[20+w] = s3; sred[24+w] = s4; }
            }
            __syncthreads();
            if (tid == 0) {
                shc[0] = sred[16]+sred[17]+sred[18]+sred[19] - sFC;
                shc[1] = sred[20]+sred[21]+sred[22]+sred[23] + sLSx - sSPx - sOMX;
                shc[2] = sred[24]+sred[25]+sred[26]+sred[27] + sLSi - sSPi - sOMN;
            }
            __syncthreads();
            float r1 = shc[0], r3 = shc[1], r4 = shc[2], WA = shc[3], WB = shc[4];
            float qmx = 0.f, qmn = 0.f;
            if (act) {
                float rtu = 2.f*bgs, rtd = 0.5f*bgs;
                float r5  = fmaxf(P + Rux - pmxv, 0.f);
                float r6  = fmaxf(pmnv - P + Rdx, 0.f);
                float r9  = fmaxf(dux - Rux, 0.f), r10 = fmaxf(ddx - Rdx, 0.f);
                float r11 = fmaxf(dui - Rux, 0.f), r12 = fmaxf(ddi - Rdx, 0.f);
                float sl = 0.f, sr = 0.f;
                if (t > 0)      { float dp = P - Pm; float rl = fmaxf(fabsf(dp) - pmxv, 0.f); sl = (dp > 0.f) ? rl : -rl; }
                if (t < Tt - 1) { float dp = Pp - P; float rl = fmaxf(fabsf(dp) - pmxv, 0.f); sr = (dp > 0.f) ? rl : -rl; }
                float nP = P - LRc * (bgs + TWO_RHO * (r1 + r5 - r6 + sl - sr));
                nP = fminf(fmaxf(nP, pmnv), pmxv);
                float nRu = fmaxf(Rux - LRc * (0.05f*bgs + TWO_RHO * (r5 - U7 - r9 - r11)), 0.f);
                float nRd = fmaxf(Rdx - LRc * (0.02f*bgs + TWO_RHO * (r6 - U8 - r10 - r12)), 0.f);
                float ndux = fmaxf(dux - LRc * (WA*rtu + TWO_RHO * ( r3 + r9 )), 0.f);
                float nddx = fmaxf(ddx - LRc * (WA*rtd + TWO_RHO * (-r3 + r10)), 0.f);
                float ndui = fmaxf(dui - LRc * (WB*rtu + TWO_RHO * ( r4 + r11)), 0.f);
                float nddi = fmaxf(ddi - LRc * (WB*rtd + TWO_RHO * (-r4 + r12)), 0.f);
                __stcg(&d_Pbuf[pw][idx], nP);
                sRu[g] = nRu; sRd[g] = nRd;
                sdux[g] = ndux; sddx[g] = nddx; sdui[g] = ndui; sddi[g] = nddi;
                if (it == ITERS - 1) { __stcg(&d_Rup[idx], nRu); __stcg(&d_Rdn[idx], nRd); }
                qmx = rtu*ndux + rtd*nddx;
                qmn = rtu*ndui + rtd*nddi;
            }
            if (tid == 0) {
                float v;
                v = fmaxf(sLSx - LRc*(WA*VOLLc + TWO_RHO*r3), 0.f); sLSx = v; qmx += VOLLc*v;
                v = fmaxf(sSPx - LRc*(WA*VOSPc - TWO_RHO*r3), 0.f); sSPx = v; qmx += VOSPc*v;
                v = fmaxf(sLSi - LRc*(WB*VOLLc + TWO_RHO*r4), 0.f); sLSi = v; qmn += VOLLc*v;
                v = fmaxf(sSPi - LRc*(WB*VOSPc - TWO_RHO*r4), 0.f); sSPi = v; qmn += VOSPc*v;
            }
            if (w < 4) {
                qmx = wsum(qmx); qmn = wsum(qmn);
                if (l == 0) { sred[16+w] = qmx; sred[20+w] = qmn; }
            }
            __syncthreads();
            if (tid == 0) {
                __stcg(&d_QmaxP[pw][bt], sred[16]+sred[17]+sred[18]+sred[19]);
                __stcg(&d_QminP[pw][bt], sred[20]+sred[21]+sred[22]+sred[23]);
            }
        }

        batch_barrier(b);    // single batch-wide barrier per iteration
    }

    // ============ finalize: (t==0, nc==0) blocks, one per batch ============
    if (t == 0 && nc == 0) {
        int bf = b;
        float s1 = 0.f;
        for (int i = tid; i < TG; i += THR) {
            int g = i % Gg, tt = i / Gg;
            float P   = __ldcg(&d_Pbuf[0][bf*TG + i]);
            float Rux = __ldcg(&d_Rup[bf*TG + i]);
            float Rdx = __ldcg(&d_Rdn[bf*TG + i]);
            float bg = bG[g];
            float C = bg * P + cG[g];
            int oi = bf*TG + g*Tt + tt;            // [b][g][t]
            out[oi] = P;
            out[BTG   + oi] = Rux;
            out[2*BTG + oi] = Rdx;
            out[3*BTG + oi] = C;
            s1 += C + 0.05f*bg*Rux + 0.02f*bg*Rdx;
        }
        float Qmax = 0.f, Qmin = 0.f;
        #pragma unroll 4
        for (int tt = 0; tt < Tt; ++tt) {
            Qmax += __ldcg(&d_QmaxP[0][bf*Tt + tt]);
            Qmin += __ldcg(&d_QminP[0][bf*Tt + tt]);
        }
        float gm = shGamma;
        float ph = 0.f;
        if (tid < Nn) {
            float Qn = 0.f;
            #pragma unroll 8
            for (int tt = 0; tt < Tt; ++tt)
                Qn += __ldcg(&d_QnP[0][(bf*Tt + tt)*Nn + tid]);
            float Ap = Qmax - gm * dmx;
            float Bp = Qmin - gm * dmn;
            float phi = fmaxf(Qn, fmaxf(Ap, Bp));
            out[4*BTG + bf*Nn + tid] = phi;
            ph = phi;
        }
        s1 = wsum(s1); ph = wsum(ph);
        if (l == 0) { sred[w] = s1; sred[16 + w] = ph; }
        __syncthreads();
        if (tid == 0) {
            float S = 0.f, PH = 0.f;
            #pragma unroll
            for (int i = 0; i < NWRP; i++) S += sred[i];
            #pragma unroll
            for (int i = 0; i < 4; i++) PH += sred[16+i];
            out[4*BTG + BN + bf]      = gm;
            out[4*BTG + BN + Bb + bf] = S + PH / (float)Nn + sEPS * gm;
        }
    }
}

extern "C" void kernel_launch(void* const* d_in, const int* in_sizes, int n_in,
                              void* d_out, int out_size) {
    const float* forecast = (const float*)d_in[0];  // [B,T]
    const float* omega    = (const float*)d_in[1];  // [B,N,T]
    const float* om_min   = (const float*)d_in[2];  // [B,T]
    const float* om_max   = (const float*)d_in[3];  // [B,T]
    const float* eps      = (const float*)d_in[4];  // [B]
    const float* pmin     = (const float*)d_in[5];  // [G]
    const float* pmax     = (const float*)d_in[6];  // [G]
    const float* bG       = (const float*)d_in[7];  // [G]
    const float* cG       = (const float*)d_in[8];  // [G]
    float* out = (float*)d_out;
    (void)in_sizes; (void)n_in; (void)out_size;

    static int attr_done = 0;
    if (!attr_done) {
        cudaFuncSetAttribute(solver, cudaFuncAttributeMaxDynamicSharedMemorySize,
                             DYN_FLOATS * (int)sizeof(float));
        attr_done = 1;
    }
    solver<<<GRID, THR, DYN_FLOATS * sizeof(float)>>>(
        forecast, omega, om_min, om_max, eps, pmin, pmax, bG, cG, out);
}

// round 17
// speedup vs baseline: 1.4590x; 1.4590x over previous
#include <cuda_runtime.h>
#include <cuda_bf16.h>

#define Bb 8
#define Nn 128
#define Gg 100
#define Tt 24
#define ITERS 40
#define LRc 2e-4f
#define TWO_RHO 20.0f
#define VOLLc 1000.0f
#define VOSPc 50.0f

#define THR  256
#define NWRP 8
#define SPW  8               // scenarios per warp (8*8 = 64 per block)
#define NSC  64              // scenarios per block

#define TG   (Tt*Gg)         // 2400
#define BTG  (Bb*TG)         // 19200
#define BN   (Bb*Nn)         // 1024
#define BT   (Bb*Tt)         // 192
#define GRID (BT*2)          // 384 blocks, 2 siblings per (b,t)
#define BPB  48              // blocks per batch

// dynamic smem layout (in floats)
#define U7_OFF  12800        // after 6400 float2 (dup,ddn interleaved)
#define U8_OFF  (U7_OFF + NWRP*104)
#define DYN_FLOATS (U8_OFF + NWRP*104)   // 14464 floats = 57856 B

// ---------------- device state (cross-block only) ----------------
__device__ float d_Pbuf[2][BTG];
__device__ float d_Rup[BTG], d_Rdn[BTG];       // written last iter only
__device__ float d_QmaxP[2][BT], d_QminP[2][BT];
__device__ float d_QnP[2][BT*Nn];              // parity buffers
__device__ float d_U7P[BT*2*Gg], d_U8P[BT*2*Gg];

// ---------------- per-batch barrier (48 blocks each) ----------------
__device__ unsigned g_cntB[Bb*32];
__device__ volatile unsigned g_genB[Bb*32];

__device__ __forceinline__ void batch_barrier(int b) {
    __syncthreads();
    if (threadIdx.x == 0) {
        int idx = b << 5;
        __threadfence();
        unsigned gen = g_genB[idx];
        if (atomicAdd(&g_cntB[idx], 1u) == (unsigned)(BPB - 1)) {
            g_cntB[idx] = 0;
            __threadfence();
            g_genB[idx] = gen + 1u;
        } else {
            while (g_genB[idx] == gen) __nanosleep(16);
        }
        __threadfence();
    }
    __syncthreads();
}

__device__ __forceinline__ float wsum(float v) {
    #pragma unroll
    for (int o = 16; o; o >>= 1) v += __shfl_down_sync(0xffffffffu, v, o);
    return v;
}
__device__ __forceinline__ void wsum2x(float& a, float& b) {
    #pragma unroll
    for (int o = 16; o; o >>= 1) {
        a += __shfl_xor_sync(0xffffffffu, a, o);
        b += __shfl_xor_sync(0xffffffffu, b, o);
    }
}
__device__ __forceinline__ void wsum2d(float& a, float& b) {
    #pragma unroll
    for (int o = 16; o; o >>= 1) {
        a += __shfl_down_sync(0xffffffffu, a, o);
        b += __shfl_down_sync(0xffffffffu, b, o);
    }
}

// ---------------- the whole solver, one launch ----------------
__global__ __launch_bounds__(THR, 3) void solver(
    const float* __restrict__ fc,   const float* __restrict__ omega,
    const float* __restrict__ omn,  const float* __restrict__ omx,
    const float* __restrict__ eps_, const float* __restrict__ pmin_,
    const float* __restrict__ pmax_,const float* __restrict__ bG,
    const float* __restrict__ cG,   float* __restrict__ out)
{
    extern __shared__ float dyn[];
    float2* duo = (float2*)dyn;          // [64][100] (dup, ddn)
    float* u7st = dyn + U7_OFF;          // [8][104]
    float* u8st = dyn + U8_OFF;          // [8][104]

    int blk = blockIdx.x, tid = threadIdx.x;
    int w = tid >> 5, l = tid & 31;
    int nc = blk & 1;
    int bt = blk >> 1;
    int t = bt % Tt, b = bt / Tt;
    int n0 = nc * NSC;

    __shared__ float shLS[NSC], shSP[NSC], shOM[NSC], shWQ[NSC];
    __shared__ float sRu[Gg], sRd[Gg];
    __shared__ float sdux[Gg], sddx[Gg], sdui[Gg], sddi[Gg];
    __shared__ float sred[32];
    __shared__ float shQm[Tt], shQi[Tt];
    __shared__ float sQn2[128];
    __shared__ float shc[8];
    __shared__ float shGamma, sLSx, sSPx, sLSi, sSPi;
    __shared__ float sFC, sOMN, sOMX, sEPS;

    // per-thread constants
    float bgv[4];
    #pragma unroll
    for (int j = 0; j < 4; ++j) {
        int g = l + 32*j;
        bgv[j] = (g < Gg) ? bG[g] : 0.f;
    }
    float bgs = 0.f, pmnv = 0.f, pmxv = 0.f;
    if (tid < Gg) { bgs = bG[tid]; pmnv = pmin_[tid]; pmxv = pmax_[tid]; }

    // ---- init ----
    for (int i = tid; i < NSC*Gg; i += THR) duo[i] = make_float2(0.f, 0.f);
    float dmx = 0.f, dmn = 0.f;
    if (tid < Nn) {
        #pragma unroll 4
        for (int tt = 0; tt < Tt; ++tt) {
            float om = omega[(b*Nn + tid)*Tt + tt];
            dmx += omx[b*Tt + tt] - om;
            dmn += om - omn[b*Tt + tt];
        }
    }
    if (tid < NSC) {
        shLS[tid] = 0.f; shSP[tid] = 0.f;
        shOM[tid] = omega[(b*Nn + n0 + tid)*Tt + t];
    }
    if (tid < Gg) {
        sRu[tid] = 0.f; sRd[tid] = 0.f;
        sdux[tid] = 0.f; sddx[tid] = 0.f; sdui[tid] = 0.f; sddi[tid] = 0.f;
    }
    if (tid == 0) {
        shGamma = 0.f; sLSx = 0.f; sSPx = 0.f; sLSi = 0.f; sSPi = 0.f;
        sFC = fc[bt]; sOMN = omn[bt]; sOMX = omx[bt]; sEPS = eps_[b];
    }
    __syncthreads();

    for (int it = 0; it < ITERS; ++it) {
        int pr = it & 1, pw = pr ^ 1;

        // ============ prologue: phi weights + gamma ============
        float gamma_old = shGamma;
        float qpart = 0.f;
        if (it > 0) {
            if (tid < Tt) shQm[tid] = __ldcg(&d_QmaxP[pr][b*Tt + tid]);
            else if (tid >= 32 && tid < 32 + Tt) shQi[tid-32] = __ldcg(&d_QminP[pr][b*Tt + tid - 32]);
            // Qn split in two 12-term halves across all 256 threads
            int n = tid & 127, h = tid >> 7;
            int t0 = h * 12;
            #pragma unroll 12
            for (int k = 0; k < 12; ++k)
                qpart += __ldcg(&d_QnP[pr][(b*Tt + t0 + k)*Nn + n]);
            if (h) sQn2[n] = qpart;
        }
        __syncthreads();

        float wa = 0.f, wb = 0.f;
        if (tid < Nn) {
            float wq;
            if (it == 0) { wq = 0.5f; wa = 0.25f; wb = 0.25f; }
            else {
                float Qmax = 0.f, Qmin = 0.f;
                #pragma unroll 8
                for (int tt = 0; tt < Tt; ++tt) { Qmax += shQm[tt]; Qmin += shQi[tt]; }
                float Qn = qpart + sQn2[tid];
                float Ap = Qmax - gamma_old * dmx;
                float Bp = Qmin - gamma_old * dmn;
                float M  = fmaxf(Ap, Bp);
                wq = (Qn > M) ? 1.f : ((Qn == M) ? 0.5f : 0.f);
                float aw = (Ap > Bp) ? 1.f : ((Ap == Bp) ? 0.5f : 0.f);
                float bw = (Bp > Ap) ? 1.f : ((Ap == Bp) ? 0.5f : 0.f);
                float wm = 1.f - wq;
                wa = wm * aw; wb = wm * bw;
            }
            if (tid >= n0 && tid < n0 + NSC)
                shWQ[tid - n0] = wq * (1.f / (float)Nn);
        }
        if (w < 4) {
            float v0 = wsum(wa), v1 = wsum(wb), v2 = wsum(wa * dmx), v3 = wsum(wb * dmn);
            if (l == 0) { sred[w] = v0; sred[4+w] = v1; sred[8+w] = v2; sred[12+w] = v3; }
        }
        __syncthreads();
        if (tid == 0) {
            float A = sred[0]+sred[1]+sred[2]+sred[3];
            float B = sred[4]+sred[5]+sred[6]+sred[7];
            float C = sred[8]+sred[9]+sred[10]+sred[11];
            float D = sred[12]+sred[13]+sred[14]+sred[15];
            float inv = 1.f / (float)Nn;
            shc[3] = A*inv; shc[4] = B*inv;
            shGamma = fmaxf(gamma_old - LRc * (sEPS - C*inv - D*inv), 0.f);
        }
        __syncthreads();

        // ============ big phase: warp w -> local scenarios w*8..w*8+7 ======
        float Ruv[4], Rdv[4];
        #pragma unroll
        for (int j = 0; j < 4; ++j) {
            int g = l + 32*j;
            Ruv[j] = (g < Gg) ? sRu[g] : 0.f;
            Rdv[j] = (g < Gg) ? sRd[g] : 0.f;
        }
        float u7a[4] = {0,0,0,0}, u8a[4] = {0,0,0,0};
        #pragma unroll
        for (int sp = 0; sp < SPW/2; ++sp) {
            int si0 = w*SPW + 2*sp, si1 = si0 + 1;
            int r0 = si0*Gg, r1 = si1*Gg;
            float du0[4], dd0[4], du1[4], dd1[4];
            #pragma unroll
            for (int j = 0; j < 4; ++j) {
                int g = l + 32*j;
                if (g < Gg) {
                    float2 v0 = duo[r0 + g]; du0[j] = v0.x; dd0[j] = v0.y;
                    float2 v1 = duo[r1 + g]; du1[j] = v1.x; dd1[j] = v1.y;
                } else { du0[j]=dd0[j]=du1[j]=dd1[j]=0.f; }
            }
            float r20 = (du0[0]-dd0[0]) + (du0[1]-dd0[1]) + (du0[2]-dd0[2]) + (du0[3]-dd0[3]);
            float r21 = (du1[0]-dd1[0]) + (du1[1]-dd1[1]) + (du1[2]-dd1[2]) + (du1[3]-dd1[3]);
            wsum2x(r20, r21);
            r20 += shLS[si0] - shSP[si0] - shOM[si0];
            r21 += shLS[si1] - shSP[si1] - shOM[si1];
            float wq0 = shWQ[si0], wq1 = shWQ[si1];
            float q0 = 0.f, q1 = 0.f;
            #pragma unroll
            for (int j = 0; j < 4; ++j) {
                int g = l + 32*j;
                if (g < Gg) {
                    float rtu = 2.0f * bgv[j], rtd = 0.5f * bgv[j];
                    float rl7 = fmaxf(du0[j] - Ruv[j], 0.f);
                    float rl8 = fmaxf(dd0[j] - Rdv[j], 0.f);
                    u7a[j] += rl7; u8a[j] += rl8;
                    float ndu = fmaxf(du0[j] - LRc * (wq0*rtu + TWO_RHO * (r20 + rl7)), 0.f);
                    float ndd = fmaxf(dd0[j] - LRc * (wq0*rtd + TWO_RHO * (rl8 - r20)), 0.f);
                    duo[r0 + g] = make_float2(ndu, ndd);
                    q0 += rtu*ndu + rtd*ndd;
                    rl7 = fmaxf(du1[j] - Ruv[j], 0.f);
                    rl8 = fmaxf(dd1[j] - Rdv[j], 0.f);
                    u7a[j] += rl7; u8a[j] += rl8;
                    ndu = fmaxf(du1[j] - LRc * (wq1*rtu + TWO_RHO * (r21 + rl7)), 0.f);
                    ndd = fmaxf(dd1[j] - LRc * (wq1*rtd + TWO_RHO * (rl8 - r21)), 0.f);
                    duo[r1 + g] = make_float2(ndu, ndd);
                    q1 += rtu*ndu + rtd*ndd;
                }
            }
            float qls0 = 0.f, qls1 = 0.f;
            if (l == 0) {
                float lsn = fmaxf(shLS[si0] - LRc * (wq0*VOLLc + TWO_RHO*r20), 0.f);
                float spn = fmaxf(shSP[si0] - LRc * (wq0*VOSPc - TWO_RHO*r20), 0.f);
                shLS[si0] = lsn; shSP[si0] = spn;
                qls0 = VOLLc*lsn + VOSPc*spn;
                lsn = fmaxf(shLS[si1] - LRc * (wq1*VOLLc + TWO_RHO*r21), 0.f);
                spn = fmaxf(shSP[si1] - LRc * (wq1*VOSPc - TWO_RHO*r21), 0.f);
                shLS[si1] = lsn; shSP[si1] = spn;
                qls1 = VOLLc*lsn + VOSPc*spn;
            }
            wsum2d(q0, q1);
            if (l == 0) {
                __stcg(&d_QnP[pw][bt*Nn + n0 + si0], q0 + qls0);
                __stcg(&d_QnP[pw][bt*Nn + n0 + si1], q1 + qls1);
            }
        }
        // stage per-warp U7/U8; publish sibling partial
        #pragma unroll
        for (int j = 0; j < 4; ++j) {
            int g = l + 32*j;
            if (g < Gg) { u7st[w*104 + g] = u7a[j]; u8st[w*104 + g] = u8a[j]; }
        }
        __syncthreads();
        if (tid < 200) {
            int g = (tid < 100) ? tid : tid - 100;
            float* src = (tid < 100) ? u7st : u8st;
            float s = 0.f;
            #pragma unroll
            for (int ww = 0; ww < NWRP; ++ww) s += src[ww*104 + g];
            if (tid < 100) __stcg(&d_U7P[(bt*2 + nc)*Gg + g], s);
            else           __stcg(&d_U8P[(bt*2 + nc)*Gg + g], s);
        }

        batch_barrier(b);    // BAR_A: U7 partials visible to sibling

        // ============ small phase (duplicated in both siblings) ============
        {
            int g = tid;
            bool act = (g < Gg);
            int idx = bt*Gg + g;
            float P=0,Pm=0,Pp=0,Rux=0,Rdx=0,dux=0,ddx=0,dui=0,ddi=0,U7=0,U8=0;
            if (act) {
                if (it == 0) { float pv = 0.5f*(pmnv + pmxv); P = pv; Pm = pv; Pp = pv; }
                else {
                    P = __ldcg(&d_Pbuf[pr][idx]);
                    if (t > 0)      Pm = __ldcg(&d_Pbuf[pr][idx - Gg]);
                    if (t < Tt - 1) Pp = __ldcg(&d_Pbuf[pr][idx + Gg]);
                }
                Rux = sRu[g]; Rdx = sRd[g];
                dux = sdux[g]; ddx = sddx[g]; dui = sdui[g]; ddi = sddi[g];
                float own7 = 0.f, own8 = 0.f;
                #pragma unroll
                for (int ww = 0; ww < NWRP; ++ww) {
                    own7 += u7st[ww*104 + g];
                    own8 += u8st[ww*104 + g];
                }
                U7 = own7 + __ldcg(&d_U7P[(bt*2 + (1 - nc))*Gg + g]);
                U8 = own8 + __ldcg(&d_U8P[(bt*2 + (1 - nc))*Gg + g]);
            }
            float s1 = 0.f, s3 = 0.f, s4 = 0.f;
            if (act) { s1 = P; s3 = dux - ddx; s4 = dui - ddi; }
            if (w < 4) {
                s1 = wsum(s1); s3 = wsum(s3); s4 = wsum(s4);
                if (l == 0) { sred[16+w] = s1; sred[20+w] = s3; sred[24+w] = s4; }
            }
            __syncthreads();
            if (tid == 0) {
                shc[0] = sred[16]+sred[17]+sred[18]+sred[19] - sFC;
                shc[1] = sred[20]+sred[21]+sred[22]+sred[23] + sLSx - sSPx - sOMX;
                shc[2] = sred[24]+sred[25]+sred[26]+sred[27] + sLSi - sSPi - sOMN;
            }
            __syncthreads();
            float r1 = shc[0], r3 = shc[1], r4 = shc[2], WA = shc[3], WB = shc[4];
            float qmx = 0.f, qmn = 0.f;
            if (act) {
                float rtu = 2.f*bgs, rtd = 0.5f*bgs;
                float r5  = fmaxf(P + Rux - pmxv, 0.f);
                float r6  = fmaxf(pmnv - P + Rdx, 0.f);
                float r9  = fmaxf(dux - Rux, 0.f), r10 = fmaxf(ddx - Rdx, 0.f);
                float r11 = fmaxf(dui - Rux, 0.f), r12 = fmaxf(ddi - Rdx, 0.f);
                float sl = 0.f, sr = 0.f;
                if (t > 0)      { float dp = P - Pm; float rl = fmaxf(fabsf(dp) - pmxv, 0.f); sl = (dp > 0.f) ? rl : -rl; }
                if (t < Tt - 1) { float dp = Pp - P; float rl = fmaxf(fabsf(dp) - pmxv, 0.f); sr = (dp > 0.f) ? rl : -rl; }
                float nP = P - LRc * (bgs + TWO_RHO * (r1 + r5 - r6 + sl - sr));
                nP = fminf(fmaxf(nP, pmnv), pmxv);
                float nRu = fmaxf(Rux - LRc * (0.05f*bgs + TWO_RHO * (r5 - U7 - r9 - r11)), 0.f);
                float nRd = fmaxf(Rdx - LRc * (0.02f*bgs + TWO_RHO * (r6 - U8 - r10 - r12)), 0.f);
                float ndux = fmaxf(dux - LRc * (WA*rtu + TWO_RHO * ( r3 + r9 )), 0.f);
                float nddx = fmaxf(ddx - LRc * (WA*rtd + TWO_RHO * (-r3 + r10)), 0.f);
                float ndui = fmaxf(dui - LRc * (WB*rtu + TWO_RHO * ( r4 + r11)), 0.f);
                float nddi = fmaxf(ddi - LRc * (WB*rtd + TWO_RHO * (-r4 + r12)), 0.f);
                __stcg(&d_Pbuf[pw][idx], nP);
                sRu[g] = nRu; sRd[g] = nRd;
                sdux[g] = ndux; sddx[g] = nddx; sdui[g] = ndui; sddi[g] = nddi;
                if (it == ITERS - 1) { __stcg(&d_Rup[idx], nRu); __stcg(&d_Rdn[idx], nRd); }
                qmx = rtu*ndux + rtd*nddx;
                qmn = rtu*ndui + rtd*nddi;
            }
            if (tid == 0) {
                float v;
                v = fmaxf(sLSx - LRc*(WA*VOLLc + TWO_RHO*r3), 0.f); sLSx = v; qmx += VOLLc*v;
                v = fmaxf(sSPx - LRc*(WA*VOSPc - TWO_RHO*r3), 0.f); sSPx = v; qmx += VOSPc*v;
                v = fmaxf(sLSi - LRc*(WB*VOLLc + TWO_RHO*r4), 0.f); sLSi = v; qmn += VOLLc*v;
                v = fmaxf(sSPi - LRc*(WB*VOSPc - TWO_RHO*r4), 0.f); sSPi = v; qmn += VOSPc*v;
            }
            if (w < 4) {
                qmx = wsum(qmx); qmn = wsum(qmn);
                if (l == 0) { sred[16+w] = qmx; sred[20+w] = qmn; }
            }
            __syncthreads();
            if (tid == 0) {
                __stcg(&d_QmaxP[pw][bt], sred[16]+sred[17]+sred[18]+sred[19]);
                __stcg(&d_QminP[pw][bt], sred[20]+sred[21]+sred[22]+sred[23]);
            }
        }

        batch_barrier(b);    // BAR_B: QmaxP/Pbuf visible for next prologue/small
    }

    // ============ finalize: (t==0, nc==0) blocks, one per batch ============
    if (t == 0 && nc == 0) {
        int bf = b;
        float s1 = 0.f;
        for (int i = tid; i < TG; i += THR) {
            int g = i % Gg, tt = i / Gg;
            float P   = __ldcg(&d_Pbuf[0][bf*TG + i]);
            float Rux = __ldcg(&d_Rup[bf*TG + i]);
            float Rdx = __ldcg(&d_Rdn[bf*TG + i]);
            float bg = bG[g];
            float C = bg * P + cG[g];
            int oi = bf*TG + g*Tt + tt;            // [b][g][t]
            out[oi] = P;
            out[BTG   + oi] = Rux;
            out[2*BTG + oi] = Rdx;
            out[3*BTG + oi] = C;
            s1 += C + 0.05f*bg*Rux + 0.02f*bg*Rdx;
        }
        float Qmax = 0.f, Qmin = 0.f;
        #pragma unroll 4
        for (int tt = 0; tt < Tt; ++tt) {
            Qmax += __ldcg(&d_QmaxP[0][bf*Tt + tt]);
            Qmin += __ldcg(&d_QminP[0][bf*Tt + tt]);
        }
        float gm = shGamma;
        float ph = 0.f;
        if (tid < Nn) {
            float Qn = 0.f;
            #pragma unroll 8
            for (int tt = 0; tt < Tt; ++tt)
                Qn += __ldcg(&d_QnP[0][(bf*Tt + tt)*Nn + tid]);
            float Ap = Qmax - gm * dmx;
            float Bp = Qmin - gm * dmn;
            float phi = fmaxf(Qn, fmaxf(Ap, Bp));
            out[4*BTG + bf*Nn + tid] = phi;
            ph = phi;
        }
        s1 = wsum(s1); ph = wsum(ph);
        if (l == 0) { sred[w] = s1; sred[16 + w] = ph; }
        __syncthreads();
        if (tid == 0) {
            float S = 0.f, PH = 0.f;
            #pragma unroll
            for (int i = 0; i < NWRP; i++) S += sred[i];
            #pragma unroll
            for (int i = 0; i < 4; i++) PH += sred[16+i];
            out[4*BTG + BN + bf]      = gm;
            out[4*BTG + BN + Bb + bf] = S + PH / (float)Nn + sEPS * gm;
        }
    }
}

extern "C" void kernel_launch(void* const* d_in, const int* in_sizes, int n_in,
                              void* d_out, int out_size) {
    const float* forecast = (const float*)d_in[0];  // [B,T]
    const float* omega    = (const float*)d_in[1];  // [B,N,T]
    const float* om_min   = (const float*)d_in[2];  // [B,T]
    const float* om_max   = (const float*)d_in[3];  // [B,T]
    const float* eps      = (const float*)d_in[4];  // [B]
    const float* pmin     = (const float*)d_in[5];  // [G]
    const float* pmax     = (const float*)d_in[6];  // [G]
    const float* bG       = (const float*)d_in[7];  // [G]
    const float* cG       = (const float*)d_in[8];  // [G]
    float* out = (float*)d_out;
    (void)in_sizes; (void)n_in; (void)out_size;

    static int attr_done = 0;
    if (!attr_done) {
        cudaFuncSetAttribute(solver, cudaFuncAttributeMaxDynamicSharedMemorySize,
                             DYN_FLOATS * (int)sizeof(float));
        attr_done = 1;
    }
    solver<<<GRID, THR, DYN_FLOATS * sizeof(float)>>>(
        forecast, omega, om_min, om_max, eps, pmin, pmax, bG, cG, out);
}